// round 4
// baseline (speedup 1.0000x reference)
#include <cuda_runtime.h>
#include <cstdint>

#define LOG2E 1.4426950408889634f

// ---------------- scratch ----------------
__device__ float g_Wh[8 * 1024 * 256];     // [b][n][h*32+d]
__device__ float g_e1[8 * 8 * 1024];
__device__ float g_e2[8 * 8 * 1024];
__device__ float g_maxe2[64];

// ---------------- f32x2 helpers ----------------
__device__ __forceinline__ void fma2(unsigned long long& d, unsigned long long a,
                                     unsigned long long b) {
    asm("fma.rn.f32x2 %0, %1, %2, %0;" : "+l"(d) : "l"(a), "l"(b));
}
__device__ __forceinline__ unsigned long long add2(unsigned long long a,
                                                   unsigned long long b) {
    unsigned long long r;
    asm("add.rn.f32x2 %0, %1, %2;" : "=l"(r) : "l"(a), "l"(b));
    return r;
}
__device__ __forceinline__ unsigned long long dup2(float v) {
    unsigned long long r;
    asm("mov.b64 %0, {%1,%1};" : "=l"(r) : "f"(v));
    return r;
}
__device__ __forceinline__ void upk2(unsigned long long v, float& lo, float& hi) {
    asm("mov.b64 {%0,%1}, %2;" : "=f"(lo), "=f"(hi) : "l"(v));
}
__device__ __forceinline__ float ex2(float x) {
    float r;
    asm("ex2.approx.ftz.f32 %0, %1;" : "=f"(r) : "f"(x));
    return r;
}

// ---------------- kernel 1: Wh = nf(8192x256) @ Wcat(256x256), FFMA2 8x8 ----------------
__global__ void __launch_bounds__(256)
gemm_wh_kernel(const float* __restrict__ A, const float* __restrict__ Wm) {
    __shared__ __align__(16) float as[16][132];   // k-major, stride 132 (528B = 33*16, aligned)
    __shared__ __align__(16) float bs[16][128];

    const int row0 = blockIdx.x * 128;
    const int col0 = blockIdx.y * 128;
    const int t = threadIdx.x;
    const int tx = t & 15, ty = t >> 4;

    unsigned long long acc[8][4];
#pragma unroll
    for (int r = 0; r < 8; r++)
#pragma unroll
        for (int c = 0; c < 4; c++) acc[r][c] = 0ull;

    // prefetch regs
    float4 a_reg[2], b_reg[2];

    auto load_tile = [&](int k0) {
#pragma unroll
        for (int l = 0; l < 2; l++) {
            int e = t + l * 256;                 // A: 512 float4s
            int r = e >> 2, kq = e & 3;
            a_reg[l] = *(const float4*)&A[(size_t)(row0 + r) * 256 + k0 + kq * 4];
            int kk = e >> 5, cq = e & 31;        // B: 512 float4s
            int c = col0 + cq * 4;
            b_reg[l] = *(const float4*)&Wm[(size_t)(c >> 5) * 8192 +
                                           (size_t)(k0 + kk) * 32 + (c & 31)];
        }
    };

    load_tile(0);

    for (int k0 = 0; k0 < 256; k0 += 16) {
        // store staged tile to smem
#pragma unroll
        for (int l = 0; l < 2; l++) {
            int e = t + l * 256;
            int r = e >> 2, kq = e & 3;
            as[kq * 4 + 0][r] = a_reg[l].x;
            as[kq * 4 + 1][r] = a_reg[l].y;
            as[kq * 4 + 2][r] = a_reg[l].z;
            as[kq * 4 + 3][r] = a_reg[l].w;
            int kk = e >> 5, cq = e & 31;
            *(float4*)&bs[kk][cq * 4] = b_reg[l];
        }
        __syncthreads();

        if (k0 + 16 < 256) load_tile(k0 + 16);

#pragma unroll
        for (int kk = 0; kk < 16; kk++) {
            float4 a0 = *(const float4*)&as[kk][ty * 4];
            float4 a1 = *(const float4*)&as[kk][ty * 4 + 64];
            ulonglong2 b0 = *(const ulonglong2*)&bs[kk][tx * 4];
            ulonglong2 b1 = *(const ulonglong2*)&bs[kk][tx * 4 + 64];
            unsigned long long ad[8];
            ad[0] = dup2(a0.x); ad[1] = dup2(a0.y); ad[2] = dup2(a0.z); ad[3] = dup2(a0.w);
            ad[4] = dup2(a1.x); ad[5] = dup2(a1.y); ad[6] = dup2(a1.z); ad[7] = dup2(a1.w);
#pragma unroll
            for (int r = 0; r < 8; r++) {
                fma2(acc[r][0], b0.x, ad[r]);
                fma2(acc[r][1], b0.y, ad[r]);
                fma2(acc[r][2], b1.x, ad[r]);
                fma2(acc[r][3], b1.y, ad[r]);
            }
        }
        __syncthreads();
    }

    // epilogue: rows {ty*4+r, 64+ty*4+r}, cols {tx*4.., 64+tx*4..}
#pragma unroll
    for (int r = 0; r < 8; r++) {
        int gr = row0 + ((r < 4) ? (ty * 4 + r) : (64 + ty * 4 + r - 4));
        float4 o0, o1;
        upk2(acc[r][0], o0.x, o0.y);
        upk2(acc[r][1], o0.z, o0.w);
        upk2(acc[r][2], o1.x, o1.y);
        upk2(acc[r][3], o1.z, o1.w);
        *(float4*)&g_Wh[(size_t)gr * 256 + col0 + tx * 4] = o0;
        *(float4*)&g_Wh[(size_t)gr * 256 + col0 + 64 + tx * 4] = o1;
    }
}

// ---------------- kernel 2: e1, e2, max(e2) per (b,h) ----------------
__global__ void compute_e_kernel(const float* __restrict__ a) {
    const int bh = blockIdx.x;
    const int b = bh >> 3, h = bh & 7;
    const int tid = threadIdx.x;
    const int warp = tid >> 5, lane = tid & 31;

    const float a1v = a[h * 64 + lane];
    const float a2v = a[h * 64 + 32 + lane];
    __shared__ float wmax[8];

    const float* base = g_Wh + (size_t)(b * 1024) * 256 + h * 32;
    float mx = -1e30f;

    for (int nn = 0; nn < 128; nn++) {
        int n = warp * 128 + nn;
        float wh = base[(size_t)n * 256 + lane];
        float x = wh * a1v;
        float y = wh * a2v;
#pragma unroll
        for (int s = 16; s >= 1; s >>= 1) {
            x += __shfl_xor_sync(0xffffffffu, x, s);
            y += __shfl_xor_sync(0xffffffffu, y, s);
        }
        if (lane == 0) {
            g_e1[bh * 1024 + n] = x;
            g_e2[bh * 1024 + n] = y;
        }
        mx = fmaxf(mx, y);
    }
    if (lane == 0) wmax[warp] = mx;
    __syncthreads();
    if (tid == 0) {
        float m = wmax[0];
#pragma unroll
        for (int w = 1; w < 8; w++) m = fmaxf(m, wmax[w]);
        g_maxe2[bh] = m;
    }
}

// ---------------- kernel 3: fused masked softmax + P @ Wh + bias + relu ----------------
// smem: Wh slice [1024x32] 128KB + e2 4KB + p-buffers 4KB/warp (duplicated pairs)
#define ATTN_SMEM ((32768 + 1024 + 16 * 1024) * 4)

__global__ void __launch_bounds__(512, 1)
gat_attn_kernel(const int* __restrict__ adj, const float* __restrict__ bias,
                float* __restrict__ out) {
    extern __shared__ __align__(16) float smem[];
    float* whs = smem;                    // 32768 floats
    float* e2s = smem + 32768;            // 1024 floats
    float* pbase = smem + 32768 + 1024;   // 16 * 1024 floats

    const int bh = blockIdx.x >> 1;
    const int hv = blockIdx.x & 1;
    const int b = bh >> 3, h = bh & 7;
    const int tid = threadIdx.x;

    // stage Wh slice of this (b,h): all 1024 j, 32 dims
    const float4* gbase = (const float4*)(g_Wh) + ((size_t)b * 1024 * 256 + h * 32) / 4;
    float4* whs4 = (float4*)whs;
    for (int f = tid; f < 8192; f += 512) {
        int j = f >> 3, q = f & 7;
        whs4[f] = gbase[(size_t)j * 64 + q];
    }
    for (int n = tid; n < 1024; n += 512) e2s[n] = g_e2[bh * 1024 + n];
    __syncthreads();

    const float maxe2 = g_maxe2[bh];
    const int warp = tid >> 5, lane = tid & 31;
    const int dg = lane & 7, jjq = lane >> 3;
    float* pw = pbase + warp * 1024;
    const float* e1p = g_e1 + bh * 1024;
    const float4 bias4 = ((const float4*)(bias + h * 32))[dg];

    for (int grp = 0; grp < 8; grp++) {
        const int i0 = hv * 512 + ((grp * 16 + warp) << 2);
        const int* adjrow = adj + (size_t)(b * 1024 + i0) * 1024;

        float e1v[4], mneg[4];
#pragma unroll
        for (int r = 0; r < 4; r++) {
            float e = e1p[i0 + r];
            e1v[r] = e;
            float s = e + maxe2;
            s = fmaxf(s, 0.2f * s);           // leaky upper bound on all scores of row i
            mneg[r] = -s * LOG2E;
        }

        unsigned long long acc[4][2];
#pragma unroll
        for (int r = 0; r < 4; r++) { acc[r][0] = 0ull; acc[r][1] = 0ull; }
        float sums[4] = {0.f, 0.f, 0.f, 0.f};

        for (int c0 = 0; c0 < 1024; c0 += 128) {
            // ---- phase A: scores+exp, lane owns 4 consecutive j ----
            const int jb = lane << 2;
            float4 ej4 = *(const float4*)&e2s[c0 + jb];
            float ej[4] = {ej4.x, ej4.y, ej4.z, ej4.w};
            float pv[4][4];
#pragma unroll
            for (int r = 0; r < 4; r++) {
                int4 a4 = *(const int4*)&adjrow[r * 1024 + c0 + jb];
                int am[4] = {a4.x, a4.y, a4.z, a4.w};
#pragma unroll
                for (int m = 0; m < 4; m++) {
                    float s = e1v[r] + ej[m];
                    s = fmaxf(s, 0.2f * s);
                    float arg = am[m] ? fmaf(s, LOG2E, mneg[r]) : -10000.0f;
                    float p = ex2(arg);
                    sums[r] += p;
                    pv[r][m] = p;
                }
            }
            // store duplicated pairs: entry(pr, m, lane) = (p_{2pr},p_{2pr},p_{2pr+1},p_{2pr+1})
#pragma unroll
            for (int m = 0; m < 4; m++) {
                *(float4*)&pw[m * 128 + jb] =
                    make_float4(pv[0][m], pv[0][m], pv[1][m], pv[1][m]);
                *(float4*)&pw[512 + m * 128 + jb] =
                    make_float4(pv[2][m], pv[2][m], pv[3][m], pv[3][m]);
            }
            __syncwarp();

            // ---- phase B: acc += P * Wh (pure LDS.128 + FFMA2) ----
            const float4* wrow = whs4 + ((size_t)c0 << 3);
            const ulonglong2* p0b = (const ulonglong2*)(pw + jjq * 128);
            const ulonglong2* p1b = (const ulonglong2*)(pw + 512 + jjq * 128);
#pragma unroll 8
            for (int blk = 0; blk < 32; blk++) {
                ulonglong2 wv = *(const ulonglong2*)(wrow + (blk << 5) + lane);
                ulonglong2 pa = p0b[blk];
                ulonglong2 pc = p1b[blk];
                fma2(acc[0][0], wv.x, pa.x); fma2(acc[0][1], wv.y, pa.x);
                fma2(acc[1][0], wv.x, pa.y); fma2(acc[1][1], wv.y, pa.y);
                fma2(acc[2][0], wv.x, pc.x); fma2(acc[2][1], wv.y, pc.x);
                fma2(acc[3][0], wv.x, pc.y); fma2(acc[3][1], wv.y, pc.y);
            }
            __syncwarp();
        }

        // reduce partial accs over the 4 jj-quarters
#pragma unroll
        for (int r = 0; r < 4; r++)
#pragma unroll
            for (int pi = 0; pi < 2; pi++) {
                acc[r][pi] = add2(acc[r][pi], __shfl_xor_sync(0xffffffffu, acc[r][pi], 8));
                acc[r][pi] = add2(acc[r][pi], __shfl_xor_sync(0xffffffffu, acc[r][pi], 16));
            }
#pragma unroll
        for (int r = 0; r < 4; r++) {
            float s = sums[r];
#pragma unroll
            for (int m = 16; m >= 1; m >>= 1) s += __shfl_xor_sync(0xffffffffu, s, m);
            sums[r] = s;
        }

        // epilogue
#pragma unroll
        for (int r = 0; r < 4; r++) {
            float inv = 1.0f / sums[r];
            float f0, f1, f2, f3;
            upk2(acc[r][0], f0, f1);
            upk2(acc[r][1], f2, f3);
            float4 o;
            o.x = fmaxf(fmaf(f0, inv, bias4.x), 0.0f);
            o.y = fmaxf(fmaf(f1, inv, bias4.y), 0.0f);
            o.z = fmaxf(fmaf(f2, inv, bias4.z), 0.0f);
            o.w = fmaxf(fmaf(f3, inv, bias4.w), 0.0f);
            if (jjq == 0) {
                *(float4*)(out + (size_t)((b << 10) + i0 + r) * 256 + (h << 5) + (dg << 2)) = o;
            }
        }
    }
}

// ---------------- launch ----------------
extern "C" void kernel_launch(void* const* d_in, const int* in_sizes, int n_in,
                              void* d_out, int out_size) {
    const float* nf   = (const float*)d_in[0];
    const int*   adj  = (const int*)d_in[1];
    const float* Wm   = (const float*)d_in[2];
    const float* av   = (const float*)d_in[3];
    const float* bias = (const float*)d_in[4];
    float* out = (float*)d_out;

    gemm_wh_kernel<<<dim3(64, 2, 1), 256>>>(nf, Wm);
    compute_e_kernel<<<64, 256>>>(av);
    cudaFuncSetAttribute(gat_attn_kernel,
                         cudaFuncAttributeMaxDynamicSharedMemorySize, ATTN_SMEM);
    gat_attn_kernel<<<128, 512, ATTN_SMEM>>>(adj, bias, out);
}

// round 8
// speedup vs baseline: 1.5995x; 1.5995x over previous
#include <cuda_runtime.h>
#include <cstdint>

#define LOG2E 1.4426950408889634f

// ---------------- scratch ----------------
__device__ float g_Wh[8 * 1024 * 256];     // [b][n][h*32+d]
__device__ float g_e1[8 * 8 * 1024];
__device__ float g_e2[8 * 8 * 1024];
__device__ float g_maxe2[64];

// ---------------- f32x2 helpers ----------------
__device__ __forceinline__ void fma2(unsigned long long& d, unsigned long long a,
                                     unsigned long long b) {
    asm("fma.rn.f32x2 %0, %1, %2, %0;" : "+l"(d) : "l"(a), "l"(b));
}
__device__ __forceinline__ unsigned long long add2(unsigned long long a,
                                                   unsigned long long b) {
    unsigned long long r;
    asm("add.rn.f32x2 %0, %1, %2;" : "=l"(r) : "l"(a), "l"(b));
    return r;
}
__device__ __forceinline__ unsigned long long dup2(float v) {
    unsigned long long r;
    asm("mov.b64 %0, {%1,%1};" : "=l"(r) : "f"(v));
    return r;
}
__device__ __forceinline__ void upk2(unsigned long long v, float& lo, float& hi) {
    asm("mov.b64 {%0,%1}, %2;" : "=f"(lo), "=f"(hi) : "l"(v));
}
__device__ __forceinline__ float ex2(float x) {
    float r;
    asm("ex2.approx.ftz.f32 %0, %1;" : "=f"(r) : "f"(x));
    return r;
}

// ---------------- kernel 1: Wh = nf(8192x256) @ Wcat(256x256), FFMA2 8x8 ----------------
__global__ void __launch_bounds__(256)
gemm_wh_kernel(const float* __restrict__ A, const float* __restrict__ Wm) {
    __shared__ __align__(16) float as[16][132];
    __shared__ __align__(16) float bs[16][128];

    const int row0 = blockIdx.x * 128;
    const int col0 = blockIdx.y * 128;
    const int t = threadIdx.x;
    const int tx = t & 15, ty = t >> 4;

    unsigned long long acc[8][4];
#pragma unroll
    for (int r = 0; r < 8; r++)
#pragma unroll
        for (int c = 0; c < 4; c++) acc[r][c] = 0ull;

    float4 a_reg[2], b_reg[2];

    auto load_tile = [&](int k0) {
#pragma unroll
        for (int l = 0; l < 2; l++) {
            int e = t + l * 256;
            int r = e >> 2, kq = e & 3;
            a_reg[l] = *(const float4*)&A[(size_t)(row0 + r) * 256 + k0 + kq * 4];
            int kk = e >> 5, cq = e & 31;
            int c = col0 + cq * 4;
            b_reg[l] = *(const float4*)&Wm[(size_t)(c >> 5) * 8192 +
                                           (size_t)(k0 + kk) * 32 + (c & 31)];
        }
    };

    load_tile(0);

    for (int k0 = 0; k0 < 256; k0 += 16) {
#pragma unroll
        for (int l = 0; l < 2; l++) {
            int e = t + l * 256;
            int r = e >> 2, kq = e & 3;
            as[kq * 4 + 0][r] = a_reg[l].x;
            as[kq * 4 + 1][r] = a_reg[l].y;
            as[kq * 4 + 2][r] = a_reg[l].z;
            as[kq * 4 + 3][r] = a_reg[l].w;
            int kk = e >> 5, cq = e & 31;
            *(float4*)&bs[kk][cq * 4] = b_reg[l];
        }
        __syncthreads();

        if (k0 + 16 < 256) load_tile(k0 + 16);

#pragma unroll
        for (int kk = 0; kk < 16; kk++) {
            float4 a0 = *(const float4*)&as[kk][ty * 4];
            float4 a1 = *(const float4*)&as[kk][ty * 4 + 64];
            ulonglong2 b0 = *(const ulonglong2*)&bs[kk][tx * 4];
            ulonglong2 b1 = *(const ulonglong2*)&bs[kk][tx * 4 + 64];
            unsigned long long ad[8];
            ad[0] = dup2(a0.x); ad[1] = dup2(a0.y); ad[2] = dup2(a0.z); ad[3] = dup2(a0.w);
            ad[4] = dup2(a1.x); ad[5] = dup2(a1.y); ad[6] = dup2(a1.z); ad[7] = dup2(a1.w);
#pragma unroll
            for (int r = 0; r < 8; r++) {
                fma2(acc[r][0], b0.x, ad[r]);
                fma2(acc[r][1], b0.y, ad[r]);
                fma2(acc[r][2], b1.x, ad[r]);
                fma2(acc[r][3], b1.y, ad[r]);
            }
        }
        __syncthreads();
    }

#pragma unroll
    for (int r = 0; r < 8; r++) {
        int gr = row0 + ((r < 4) ? (ty * 4 + r) : (64 + ty * 4 + r - 4));
        float4 o0, o1;
        upk2(acc[r][0], o0.x, o0.y);
        upk2(acc[r][1], o0.z, o0.w);
        upk2(acc[r][2], o1.x, o1.y);
        upk2(acc[r][3], o1.z, o1.w);
        *(float4*)&g_Wh[(size_t)gr * 256 + col0 + tx * 4] = o0;
        *(float4*)&g_Wh[(size_t)gr * 256 + col0 + 64 + tx * 4] = o1;
    }
}

// ---------------- kernel 2: e1, e2, max(e2) per (b,h) ----------------
__global__ void compute_e_kernel(const float* __restrict__ a) {
    const int bh = blockIdx.x;
    const int b = bh >> 3, h = bh & 7;
    const int tid = threadIdx.x;
    const int warp = tid >> 5, lane = tid & 31;

    const float a1v = a[h * 64 + lane];
    const float a2v = a[h * 64 + 32 + lane];
    __shared__ float wmax[8];

    const float* base = g_Wh + (size_t)(b * 1024) * 256 + h * 32;
    float mx = -1e30f;

    for (int nn = 0; nn < 128; nn++) {
        int n = warp * 128 + nn;
        float wh = base[(size_t)n * 256 + lane];
        float x = wh * a1v;
        float y = wh * a2v;
#pragma unroll
        for (int s = 16; s >= 1; s >>= 1) {
            x += __shfl_xor_sync(0xffffffffu, x, s);
            y += __shfl_xor_sync(0xffffffffu, y, s);
        }
        if (lane == 0) {
            g_e1[bh * 1024 + n] = x;
            g_e2[bh * 1024 + n] = y;
        }
        mx = fmaxf(mx, y);
    }
    if (lane == 0) wmax[warp] = mx;
    __syncthreads();
    if (tid == 0) {
        float m = wmax[0];
#pragma unroll
        for (int w = 1; w < 8; w++) m = fmaxf(m, wmax[w]);
        g_maxe2[bh] = m;
    }
}

// ---------------- kernel 3: fused masked softmax + P @ Wh + bias + relu ----------------
// R=8 rows/warp-group. p-buffer: 2 banks (rows0-3, rows4-7), 4 sections of 33
// float4 each (pad 1/section -> reader addrs jjq*33+blk hit distinct bank quads).
// smem: Wh 128KB + e2 4KB + p 16*1056 floats = 198KB total.
#define PW_WARP 1056
#define ATTN_SMEM ((32768 + 1024 + 16 * PW_WARP) * 4)

__global__ void __launch_bounds__(512, 1)
gat_attn_kernel(const int* __restrict__ adj, const float* __restrict__ bias,
                float* __restrict__ out) {
    extern __shared__ __align__(16) float smem[];
    float* whs = smem;                    // 32768 floats
    float* e2s = smem + 32768;            // 1024 floats
    float* pbase = smem + 32768 + 1024;   // 16 * 1056 floats

    const int bh = blockIdx.x >> 1;
    const int hv = blockIdx.x & 1;
    const int b = bh >> 3, h = bh & 7;
    const int tid = threadIdx.x;

    // stage Wh slice of this (b,h): all 1024 j, 32 dims
    const float4* gbase = (const float4*)(g_Wh) + ((size_t)b * 1024 * 256 + h * 32) / 4;
    float4* whs4 = (float4*)whs;
    for (int f = tid; f < 8192; f += 512) {
        int j = f >> 3, q = f & 7;
        whs4[f] = gbase[(size_t)j * 64 + q];
    }
    for (int n = tid; n < 1024; n += 512) e2s[n] = g_e2[bh * 1024 + n];
    __syncthreads();

    const float maxe2 = g_maxe2[bh];
    const int warp = tid >> 5, lane = tid & 31;
    const int dg = lane & 7, jjq = lane >> 3;
    float* pw = pbase + warp * PW_WARP;           // bufA: [0,528), bufB: [528,1056)
    const float* e1p = g_e1 + bh * 1024;
    const float4 bias4 = ((const float4*)(bias + h * 32))[dg];

    // reader base offsets (16B units): jjq*33 within each buffer
    const float* prA = pw + jjq * 33 * 4;
    const float* prB = pw + 528 + jjq * 33 * 4;

    for (int grp = 0; grp < 4; grp++) {
        const int i0 = hv * 512 + ((grp * 16 + warp) << 3);   // 8-row group
        const int* adjrow = adj + (size_t)(b * 1024 + i0) * 1024;

        float e1v[8], mneg[8];
        float4 e14a = *(const float4*)&e1p[i0];
        float4 e14b = *(const float4*)&e1p[i0 + 4];
        e1v[0] = e14a.x; e1v[1] = e14a.y; e1v[2] = e14a.z; e1v[3] = e14a.w;
        e1v[4] = e14b.x; e1v[5] = e14b.y; e1v[6] = e14b.z; e1v[7] = e14b.w;
#pragma unroll
        for (int r = 0; r < 8; r++) {
            float s = e1v[r] + maxe2;
            s = fmaxf(s, 0.2f * s);           // leaky upper bound on all scores of row i
            mneg[r] = -s * LOG2E;
        }

        unsigned long long acc[8][2];
#pragma unroll
        for (int r = 0; r < 8; r++) { acc[r][0] = 0ull; acc[r][1] = 0ull; }
        float sums[8] = {0.f, 0.f, 0.f, 0.f, 0.f, 0.f, 0.f, 0.f};

        for (int c0 = 0; c0 < 1024; c0 += 128) {
            // ---- phase A: scores+exp, lane owns 4 consecutive j, 8 rows ----
            const int jb = lane << 2;
            float4 ej4 = *(const float4*)&e2s[c0 + jb];
            float ej[4] = {ej4.x, ej4.y, ej4.z, ej4.w};
            float pv[8][4];
#pragma unroll
            for (int r = 0; r < 8; r++) {
                int4 a4 = *(const int4*)&adjrow[r * 1024 + c0 + jb];
                int am[4] = {a4.x, a4.y, a4.z, a4.w};
#pragma unroll
                for (int m = 0; m < 4; m++) {
                    float s = e1v[r] + ej[m];
                    s = fmaxf(s, 0.2f * s);
                    float arg = am[m] ? fmaf(s, LOG2E, mneg[r]) : -10000.0f;
                    float p = ex2(arg);
                    pv[r][m] = p;
                }
                sums[r] += (pv[r][0] + pv[r][1]) + (pv[r][2] + pv[r][3]);
            }
            // store: section m (stride 33 float4), lane-contiguous (conflict-free)
#pragma unroll
            for (int m = 0; m < 4; m++) {
                *(float4*)&pw[(m * 33 + lane) * 4] =
                    make_float4(pv[0][m], pv[1][m], pv[2][m], pv[3][m]);
                *(float4*)&pw[528 + (m * 33 + lane) * 4] =
                    make_float4(pv[4][m], pv[5][m], pv[6][m], pv[7][m]);
            }
            __syncwarp();

            // ---- phase B: acc += P * Wh. reader j = c0 + blk*4 + jjq ----
            // row stride: 4 j-rows per blk * 8 sixteen-byte granules per row = 32
            const ulonglong2* wrow =
                (const ulonglong2*)(whs4 + (size_t)(c0 + jjq) * 8 + dg);
#pragma unroll 4
            for (int blk = 0; blk < 32; blk++) {
                ulonglong2 wv = wrow[blk * 32];
                float4 pa = *(const float4*)(prA + blk * 4);  // rows 0-3
                float4 pb = *(const float4*)(prB + blk * 4);  // rows 4-7
                unsigned long long pp;
                pp = dup2(pa.x); fma2(acc[0][0], wv.x, pp); fma2(acc[0][1], wv.y, pp);
                pp = dup2(pa.y); fma2(acc[1][0], wv.x, pp); fma2(acc[1][1], wv.y, pp);
                pp = dup2(pa.z); fma2(acc[2][0], wv.x, pp); fma2(acc[2][1], wv.y, pp);
                pp = dup2(pa.w); fma2(acc[3][0], wv.x, pp); fma2(acc[3][1], wv.y, pp);
                pp = dup2(pb.x); fma2(acc[4][0], wv.x, pp); fma2(acc[4][1], wv.y, pp);
                pp = dup2(pb.y); fma2(acc[5][0], wv.x, pp); fma2(acc[5][1], wv.y, pp);
                pp = dup2(pb.z); fma2(acc[6][0], wv.x, pp); fma2(acc[6][1], wv.y, pp);
                pp = dup2(pb.w); fma2(acc[7][0], wv.x, pp); fma2(acc[7][1], wv.y, pp);
            }
            __syncwarp();
        }

        // reduce partial accs over the 4 jj-quarters (lanes xor 8, 16)
#pragma unroll
        for (int r = 0; r < 8; r++)
#pragma unroll
            for (int pi = 0; pi < 2; pi++) {
                acc[r][pi] = add2(acc[r][pi], __shfl_xor_sync(0xffffffffu, acc[r][pi], 8));
                acc[r][pi] = add2(acc[r][pi], __shfl_xor_sync(0xffffffffu, acc[r][pi], 16));
            }
#pragma unroll
        for (int r = 0; r < 8; r++) {
            float s = sums[r];
#pragma unroll
            for (int m = 16; m >= 1; m >>= 1) s += __shfl_xor_sync(0xffffffffu, s, m);
            sums[r] = s;
        }

        // epilogue: normalize, +bias, relu, store (lanes 0..7 store)
#pragma unroll
        for (int r = 0; r < 8; r++) {
            float inv = 1.0f / sums[r];
            float f0, f1, f2, f3;
            upk2(acc[r][0], f0, f1);
            upk2(acc[r][1], f2, f3);
            float4 o;
            o.x = fmaxf(fmaf(f0, inv, bias4.x), 0.0f);
            o.y = fmaxf(fmaf(f1, inv, bias4.y), 0.0f);
            o.z = fmaxf(fmaf(f2, inv, bias4.z), 0.0f);
            o.w = fmaxf(fmaf(f3, inv, bias4.w), 0.0f);
            if (jjq == 0) {
                *(float4*)(out + (size_t)((b << 10) + i0 + r) * 256 + (h << 5) + (dg << 2)) = o;
            }
        }
    }
}

// ---------------- launch ----------------
extern "C" void kernel_launch(void* const* d_in, const int* in_sizes, int n_in,
                              void* d_out, int out_size) {
    const float* nf   = (const float*)d_in[0];
    const int*   adj  = (const int*)d_in[1];
    const float* Wm   = (const float*)d_in[2];
    const float* av   = (const float*)d_in[3];
    const float* bias = (const float*)d_in[4];
    float* out = (float*)d_out;

    gemm_wh_kernel<<<dim3(64, 2, 1), 256>>>(nf, Wm);
    compute_e_kernel<<<64, 256>>>(av);
    cudaFuncSetAttribute(gat_attn_kernel,
                         cudaFuncAttributeMaxDynamicSharedMemorySize, ATTN_SMEM);
    gat_attn_kernel<<<128, 512, ATTN_SMEM>>>(adj, bias, out);
}